// round 15
// baseline (speedup 1.0000x reference)
#include <cuda_runtime.h>
#include <cuda_fp16.h>
#include <cstdint>
#include <cstddef>

constexpr int kB = 128, kT = 256, kI = 256, kH = 512, kO = 128;
constexpr int kBH = kB * kH;

// ---------------- Global scratch ----------------
__device__ uint4 g_xf[kT][2][2048];   // x fragments (K=256)
__device__ uint4 g_h1f[3][2][4096];   // h1 ring (K=512)
__device__ uint4 g_h2f[3][2][4096];   // h2 ring
__device__ float g_h2p[kBH];          // plain final h2 for FC
// Progress counters (one array -> one memset -> ncu -s5 lands on k_scan):
// g_fl[0][mcta][ncta] += 1 per warp after epi1; complete at 16*(it+1).
// g_fl[1][mcta][ncta] += 1 per warp after epi2; complete at 16*it.
__device__ unsigned g_fl[2][2][64];

constexpr int GRID = 128, NTHR = 512;

// ---------------- SMEM layout (bytes) ----------------
constexpr int SB_WHH0 = 0;        // 32 cols x 512 k fp16 = 32768 B
constexpr int SB_WI1  = 32768;
constexpr int SB_WHH1 = 65536;
constexpr int SB_WI0  = 98304;    // 32 cols x 256 k fp16 = 16384 B
constexpr int CEX_LD  = 34;
constexpr int SB_CEXA = 114688;   // float[4*64*34] = 34816 B
constexpr int SB_CEXB = 149504;
constexpr int SB_B1   = 184320;   // float[32]
constexpr int SB_B2   = 184448;
constexpr size_t SMEM_BYTES = 184576;

__device__ __forceinline__ float to_tf32(float x) {
    uint32_t u;
    asm("cvt.rna.tf32.f32 %0, %1;" : "=r"(u) : "f"(x));
    return __uint_as_float(u);
}

__device__ __forceinline__ void mma_f16(float* d, const uint32_t* a, const uint32_t* b) {
    asm volatile(
        "mma.sync.aligned.m16n8k16.row.col.f32.f16.f16.f32 "
        "{%0,%1,%2,%3}, {%4,%5,%6,%7}, {%8,%9}, {%0,%1,%2,%3};\n"
        : "+f"(d[0]), "+f"(d[1]), "+f"(d[2]), "+f"(d[3])
        : "r"(a[0]), "r"(a[1]), "r"(a[2]), "r"(a[3]), "r"(b[0]), "r"(b[1]));
}

__device__ __forceinline__ void mma_tf32(float* d, const uint32_t* a, const uint32_t* b) {
    asm volatile(
        "mma.sync.aligned.m16n8k8.row.col.f32.tf32.tf32.f32 "
        "{%0,%1,%2,%3}, {%4,%5,%6,%7}, {%8,%9}, {%0,%1,%2,%3};\n"
        : "+f"(d[0]), "+f"(d[1]), "+f"(d[2]), "+f"(d[3])
        : "r"(a[0]), "r"(a[1]), "r"(a[2]), "r"(a[3]), "r"(b[0]), "r"(b[1]));
}

// Fast activations (ex2.approx + rcp.approx): abs err ~3e-5 / ~6e-5.
__device__ __forceinline__ float fsigm(float x) {
    float t;
    asm("ex2.approx.f32 %0, %1;" : "=f"(t) : "f"(-x * 1.4426950408889634f));
    float r;
    asm("rcp.approx.f32 %0, %1;" : "=f"(r) : "f"(1.0f + t));
    return r;
}
__device__ __forceinline__ float ftanh(float x) {
    return 2.0f * fsigm(2.0f * x) - 1.0f;
}

// =====================================================================
// One-time x transpose into fp16 fragment layout.
// =====================================================================
__global__ void __launch_bounds__(256) k_prep(const float* __restrict__ x)
{
    __shared__ float tile[64][68];
    const int tid = threadIdx.x;
    const int u = blockIdx.x;
    const int ch = u & 3, mc = (u >> 2) & 1, t = u >> 3;

#pragma unroll
    for (int p = 0; p < 4; ++p) {
        const int v = tid + p * 256;
        const int r = v >> 4, k4 = v & 15;
        const float4 val = __ldg((const float4*)&x[
            (size_t)(mc * 64 + r) * (kT * kI) + (size_t)t * kI + ch * 64 + k4 * 4]);
        *(float4*)&tile[r][k4 * 4] = val;
    }
    __syncthreads();

    uint32_t* dst = (uint32_t*)&g_xf[t][mc][ch * 512];
#pragma unroll
    for (int p = 0; p < 8; ++p) {
        const int widx = tid + p * 256;
        const int gl   = widx >> 9;
        const int mt   = (widx >> 7) & 3;
        const int lane = (widx >> 2) & 31;
        const int reg  = widx & 3;
        const int r = mt * 16 + (lane >> 2) + ((reg & 1) << 3);
        const int k = gl * 16 + ((lane & 3) << 1) + ((reg >> 1) << 3);
        __half2 hv = __floats2half2_rn(tile[r][k], tile[r][k + 1]);
        dst[widx] = *(uint32_t*)&hv;
    }
}

// =====================================================================
// Persistent fused 2-layer LSTM scan, fp16 / fp32-acc, counter flags with
// warp-granular release (syncwarp + lane0 red.release).
// =====================================================================
__global__ void __launch_bounds__(NTHR, 1) k_scan(
    const float* __restrict__ Wih0, const float* __restrict__ Whh0,
    const float* __restrict__ Wih1, const float* __restrict__ Whh1,
    const float* __restrict__ bih0, const float* __restrict__ bhh0,
    const float* __restrict__ bih1, const float* __restrict__ bhh1)
{
    extern __shared__ char smc[];
    __half* WHH0h = (__half*)(smc + SB_WHH0);
    __half* WI1h  = (__half*)(smc + SB_WI1);
    __half* WHH1h = (__half*)(smc + SB_WHH1);
    __half* WI0h  = (__half*)(smc + SB_WI0);
    const uint32_t* BWH0 = (const uint32_t*)(smc + SB_WHH0);
    const uint32_t* BWI1 = (const uint32_t*)(smc + SB_WI1);
    const uint32_t* BWH1 = (const uint32_t*)(smc + SB_WHH1);
    const uint32_t* BWI0 = (const uint32_t*)(smc + SB_WI0);
    float* CEXA = (float*)(smc + SB_CEXA);
    float* CEXB = (float*)(smc + SB_CEXB);
    float* B1 = (float*)(smc + SB_B1);
    float* B2 = (float*)(smc + SB_B2);

    const int tid  = threadIdx.x;
    const int lane = tid & 31;
    const int w    = tid >> 5;
    const int kq   = w & 3;
    const int mw   = w >> 2;
    const int mcta = blockIdx.x & 1;
    const int ncta = blockIdx.x >> 1;
    const int hbase = ncta * 8;
    const int row0  = mcta * 64;

    // ---- Weight slices into SMEM as fp16 fragments ----
    for (int i = tid; i < 32 * 512; i += NTHR) {
        const int cc = i >> 9, k = i & 511;
        const int grow = (cc >> 3) * kH + hbase + (cc & 7);
        const int idx = ((((k >> 4) * 4 + (cc >> 3)) * 32 +
                          (((cc & 7) << 2) | ((k & 7) >> 1))) << 2) +
                        (((k >> 3) & 1) << 1) + (k & 1);
        WHH0h[idx] = __float2half(Whh0[grow * kH + k]);
        WI1h[idx]  = __float2half(Wih1[grow * kH + k]);
        WHH1h[idx] = __float2half(Whh1[grow * kH + k]);
    }
    for (int i = tid; i < 32 * 256; i += NTHR) {
        const int cc = i >> 8, k = i & 255;
        const int grow = (cc >> 3) * kH + hbase + (cc & 7);
        const int idx = ((((k >> 4) * 4 + (cc >> 3)) * 32 +
                          (((cc & 7) << 2) | ((k & 7) >> 1))) << 2) +
                        (((k >> 3) & 1) << 1) + (k & 1);
        WI0h[idx] = __float2half(Wih0[grow * kI + k]);
    }
    if (tid < 32) {
        const int grow = (tid >> 3) * kH + hbase + (tid & 7);
        B1[tid] = bih0[grow] + bhh0[grow];
        B2[tid] = bih1[grow] + bhh1[grow];
    }
    __syncthreads();

    const int er = tid >> 3;
    const int ej = tid & 7;
    const int hg  = ncta >> 1;
    const int hkl = ((ncta & 1) << 3) + ej;
    const int hmt = er >> 4;
    const int hr16 = er & 15;
    const int hlane = ((hr16 & 7) << 2) | ((hkl & 7) >> 1);
    const int hreg  = ((hr16 >> 3) & 1) | (((hkl >> 3) & 1) << 1);
    const int hhalf = hkl & 1;
    const int hflat = ((((hg * 4 + hmt) * 32 + hlane) * 4) + hreg) * 2 + hhalf;

    float c1s = 0.f, c2s = 0.f;

    auto wait_flags = [&](const unsigned* fb, unsigned need) {
        const unsigned* p = fb + kq * 16 + (lane & 15);
        bool ok;
        do {
            unsigned v;
            asm volatile("ld.acquire.gpu.u32 %0, [%1];"
                         : "=r"(v) : "l"(p) : "memory");
            ok = (v >= need);
        } while (__ballot_sync(0xffffffffu, ok) != 0xffffffffu);
    };
    // Warp-granular release: lane0 adds +1 after this warp's stores.
    auto warp_signal = [&](unsigned* flg) {
        __syncwarp();
        if (lane == 0)
            asm volatile("red.release.gpu.global.add.u32 [%0], %1;"
                         :: "l"(flg), "r"(1u) : "memory");
    };

    uint4 ring[8];
    uint4 xa[4];
    float acc1[4][4], acc2[4][4];

    // ---- Prologue: X(0) -> acc1, load h1 ring (buf 0, zeroed) ----
#pragma unroll
    for (int j = 0; j < 4; ++j)
        xa[j] = __ldcg(&g_xf[0][mcta][((kq * 4 + j) * 4 + mw) * 32 + lane]);
#pragma unroll
    for (int t = 0; t < 4; ++t)
#pragma unroll
        for (int q = 0; q < 4; ++q) acc1[t][q] = 0.f;
#pragma unroll
    for (int j = 0; j < 4; ++j) {
        const int g = kq * 4 + j;
        uint32_t au[4] = { xa[j].x, xa[j].y, xa[j].z, xa[j].w };
#pragma unroll
        for (int t = 0; t < 4; ++t) {
            const uint2 bb = *(const uint2*)&BWI0[((g * 4 + t) * 32 + lane) * 2];
            uint32_t bu[2] = { bb.x, bb.y };
            mma_f16(acc1[t], au, bu);
        }
    }
    {
        const uint4* h1b = &g_h1f[0][mcta][0];
#pragma unroll
        for (int j = 0; j < 8; ++j)
            ring[j] = __ldcg(&h1b[((kq * 8 + j) * 4 + mw) * 32 + lane]);
    }

    int b_cur = 0, b_nxt = 1;

    for (int it = 0; it <= kT; ++it) {
        const bool do1 = (it < kT);
        const bool do2 = (it >= 1);

        // WAR guard for final iteration: epi2(kT) rewrites CEXB while no
        // epi1 bar exists on this path; align warps first.
        if (!do1) __syncthreads();

#pragma unroll
        for (int t = 0; t < 4; ++t)
#pragma unroll
            for (int q = 0; q < 4; ++q) acc2[t][q] = 0.f;

        // prefetch x frags for X(it+1)
        if (it + 1 < kT) {
#pragma unroll
            for (int j = 0; j < 4; ++j)
                xa[j] = __ldcg(&g_xf[it + 1][mcta][((kq * 4 + j) * 4 + mw) * 32 + lane]);
        }

        const int r  = mw * 16 + (lane >> 2);
        const int cb = (lane & 3) * 2;

        // ---- H1a: h1 @ Whh0 -> acc1 (ring preserved) ----
        if (do1) {
#pragma unroll
            for (int j = 0; j < 8; ++j) {
                const uint4 af = ring[j];
                uint32_t au[4] = { af.x, af.y, af.z, af.w };
                const int g = kq * 8 + j;
#pragma unroll
                for (int t = 0; t < 4; ++t) {
                    const uint2 bb = *(const uint2*)&BWH0[((g * 4 + t) * 32 + lane) * 2];
                    uint32_t bu[2] = { bb.x, bb.y };
                    mma_f16(acc1[t], au, bu);
                }
            }

            // ---- epi1: reduce, cell update, store h1[it], warp-signal ----
#pragma unroll
            for (int t = 0; t < 4; ++t) {
                float* cx = &CEXA[(kq * 64 + r) * CEX_LD + t * 8 + cb];
                *(float2*)cx                = make_float2(acc1[t][0], acc1[t][1]);
                *(float2*)(cx + 8 * CEX_LD) = make_float2(acc1[t][2], acc1[t][3]);
            }
            __syncthreads();
            float pre[4];
#pragma unroll
            for (int g = 0; g < 4; ++g) {
                float s = B1[g * 8 + ej];
#pragma unroll
                for (int q = 0; q < 4; ++q)
                    s += CEXA[(q * 64 + er) * CEX_LD + g * 8 + ej];
                pre[g] = s;
            }
            const float ig = fsigm(pre[0]), fg = fsigm(pre[1]);
            const float gg = ftanh(pre[2]), og = fsigm(pre[3]);
            const float cn = fg * c1s + ig * gg;
            c1s = cn;
            ((__half*)&g_h1f[b_nxt][mcta][0])[hflat] = __float2half(og * ftanh(cn));
            warp_signal(&g_fl[0][mcta][ncta]);
            // WAR guard: at it==0 there is no epi2 bar before the next CEXA
            // write; re-align warps once.
            if (it == 0) __syncthreads();
        }

        // ---- H1b + H2 + epi2 (off the f1 chain) ----
        if (do2) {
            if (it >= 2) wait_flags(&g_fl[1][mcta][0], 16u * (unsigned)(it - 1));
            const uint4* h2b = &g_h2f[b_cur][mcta][0];

#pragma unroll
            for (int j = 0; j < 8; ++j) {
                const uint4 af = ring[j];
                ring[j] = __ldcg(&h2b[((kq * 8 + j) * 4 + mw) * 32 + lane]);
                uint32_t au[4] = { af.x, af.y, af.z, af.w };
                const int g = kq * 8 + j;
#pragma unroll
                for (int t = 0; t < 4; ++t) {
                    const uint2 bb = *(const uint2*)&BWI1[((g * 4 + t) * 32 + lane) * 2];
                    uint32_t bu[2] = { bb.x, bb.y };
                    mma_f16(acc2[t], au, bu);
                }
            }
#pragma unroll
            for (int j = 0; j < 8; ++j) {
                const uint4 af = ring[j];
                uint32_t au[4] = { af.x, af.y, af.z, af.w };
                const int g = kq * 8 + j;
#pragma unroll
                for (int t = 0; t < 4; ++t) {
                    const uint2 bb = *(const uint2*)&BWH1[((g * 4 + t) * 32 + lane) * 2];
                    uint32_t bu[2] = { bb.x, bb.y };
                    mma_f16(acc2[t], au, bu);
                }
            }

#pragma unroll
            for (int t = 0; t < 4; ++t) {
                float* cx = &CEXB[(kq * 64 + r) * CEX_LD + t * 8 + cb];
                *(float2*)cx                = make_float2(acc2[t][0], acc2[t][1]);
                *(float2*)(cx + 8 * CEX_LD) = make_float2(acc2[t][2], acc2[t][3]);
            }
            __syncthreads();
            float pre[4];
#pragma unroll
            for (int g = 0; g < 4; ++g) {
                float s = B2[g * 8 + ej];
#pragma unroll
                for (int q = 0; q < 4; ++q)
                    s += CEXB[(q * 64 + er) * CEX_LD + g * 8 + ej];
                pre[g] = s;
            }
            const float ig = fsigm(pre[0]), fg = fsigm(pre[1]);
            const float gg = ftanh(pre[2]), og = fsigm(pre[3]);
            const float cn = fg * c2s + ig * gg;
            c2s = cn;
            const float hv = og * ftanh(cn);
            ((__half*)&g_h2f[b_nxt][mcta][0])[hflat] = __float2half(hv);
            if (it == kT) g_h2p[(row0 + er) * kH + hbase + ej] = hv;
            warp_signal(&g_fl[1][mcta][ncta]);
        }

        // ---- X(it+1) inside the wait window ----
        if (it + 1 < kT) {
#pragma unroll
            for (int t = 0; t < 4; ++t)
#pragma unroll
                for (int q = 0; q < 4; ++q) acc1[t][q] = 0.f;
#pragma unroll
            for (int j = 0; j < 4; ++j) {
                const int g = kq * 4 + j;
                uint32_t au[4] = { xa[j].x, xa[j].y, xa[j].z, xa[j].w };
#pragma unroll
                for (int t = 0; t < 4; ++t) {
                    const uint2 bb = *(const uint2*)&BWI0[((g * 4 + t) * 32 + lane) * 2];
                    uint32_t bu[2] = { bb.x, bb.y };
                    mma_f16(acc1[t], au, bu);
                }
            }
        }

        // ---- handoff: wait f1 complete for it, issue h1[it] ring loads ----
        if (it < kT) {
            wait_flags(&g_fl[0][mcta][0], 16u * (unsigned)(it + 1));
            const uint4* h1b = &g_h1f[b_nxt][mcta][0];
#pragma unroll
            for (int j = 0; j < 8; ++j)
                ring[j] = __ldcg(&h1b[((kq * 8 + j) * 4 + mw) * 32 + lane]);
        }

        b_cur = b_nxt;
        b_nxt = b_nxt + 1;
        if (b_nxt == 3) b_nxt = 0;
    }
}

// =====================================================================
// FC head: out = h2_final @ fc_w^T + fc_b
// =====================================================================
__global__ __launch_bounds__(256) void k_fc(
    const float* __restrict__ A0, const float* __restrict__ W0,
    const float* __restrict__ bias0, float* __restrict__ outp)
{
    __shared__ float Asf[512];
    __shared__ float Bsf[2048];

    const int tid  = threadIdx.x;
    const int lane = tid & 31;
    const int w    = tid >> 5;
    const int mw   = w >> 2;
    const int nw   = w & 3;
    const int mtile = blockIdx.y;

    float acc[4][4];
#pragma unroll
    for (int j = 0; j < 4; j++)
#pragma unroll
        for (int q = 0; q < 4; q++) acc[j][q] = 0.0f;

    const int a_r  = tid >> 3;
    const int a_kk = (tid & 7) * 2;
    const int b_n   = tid >> 1;
    const int b_kk8 = (tid & 1) * 8;

#pragma unroll 1
    for (int kt = 0; kt < kH; kt += 16) {
        {
            const int gm = mtile * 32 + a_r;
            const float2 v = *(const float2*)&A0[(size_t)gm * kH + kt + a_kk];
            const float vv[2] = { v.x, v.y };
#pragma unroll
            for (int e = 0; e < 2; ++e) {
                const int k = a_kk + e;
                const int g = (k >> 3) * 2 + (a_r >> 4);
                const int ln = ((a_r & 7) << 2) | (k & 3);
                const int comp = ((a_r >> 3) & 1) | (((k >> 2) & 1) << 1);
                Asf[(g * 32 + ln) * 4 + comp] = to_tf32(vv[e]);
            }
        }
        {
            const float4* p = (const float4*)&W0[(size_t)b_n * kH + kt + b_kk8];
            const float4 v0 = p[0], v1 = p[1];
            const float vv[8] = { v0.x, v0.y, v0.z, v0.w, v1.x, v1.y, v1.z, v1.w };
#pragma unroll
            for (int e = 0; e < 8; ++e) {
                const int k = b_kk8 + e;
                const int g = (k >> 3) * 16 + (b_n >> 3);
                const int ln = ((b_n & 7) << 2) | (k & 3);
                const int comp = (k >> 2) & 1;
                Bsf[(g * 32 + ln) * 2 + comp] = to_tf32(vv[e]);
            }
        }
        __syncthreads();

#pragma unroll
        for (int k8 = 0; k8 < 2; ++k8) {
            const float4 af = *(const float4*)&Asf[((k8 * 2 + mw) * 32 + lane) * 4];
            uint32_t au[4] = { __float_as_uint(af.x), __float_as_uint(af.y),
                               __float_as_uint(af.z), __float_as_uint(af.w) };
#pragma unroll
            for (int j = 0; j < 4; ++j) {
                const float2 b = *(const float2*)&Bsf[((k8 * 16 + nw * 4 + j) * 32 + lane) * 2];
                uint32_t bu[2] = { __float_as_uint(b.x), __float_as_uint(b.y) };
                mma_tf32(acc[j], au, bu);
            }
        }
        __syncthreads();
    }

    const int gr = mtile * 32 + mw * 16 + (lane >> 2);
    const int cbase = nw * 32 + (lane & 3) * 2;
#pragma unroll
    for (int j = 0; j < 4; j++) {
        const int c0 = cbase + j * 8;
        const float bv0 = bias0[c0];
        const float bv1 = bias0[c0 + 1];
        outp[(size_t)gr * kO + c0]           = acc[j][0] + bv0;
        outp[(size_t)gr * kO + c0 + 1]       = acc[j][1] + bv1;
        outp[(size_t)(gr + 8) * kO + c0]     = acc[j][2] + bv0;
        outp[(size_t)(gr + 8) * kO + c0 + 1] = acc[j][3] + bv1;
    }
}

extern "C" void kernel_launch(void* const* d_in, const int* in_sizes, int n_in,
                              void* d_out, int out_size)
{
    const float* x     = (const float*)d_in[0];
    const float* W_ih0 = (const float*)d_in[1];
    const float* W_hh0 = (const float*)d_in[2];
    const float* b_ih0 = (const float*)d_in[3];
    const float* b_hh0 = (const float*)d_in[4];
    const float* W_ih1 = (const float*)d_in[5];
    const float* W_hh1 = (const float*)d_in[6];
    const float* b_ih1 = (const float*)d_in[7];
    const float* b_hh1 = (const float*)d_in[8];
    const float* fc_w  = (const float*)d_in[9];
    const float* fc_b  = (const float*)d_in[10];

    void *h1fp, *h2fp, *h2pp, *flp;
    cudaGetSymbolAddress(&h1fp, g_h1f);
    cudaGetSymbolAddress(&h2fp, g_h2f);
    cudaGetSymbolAddress(&h2pp, g_h2p);
    cudaGetSymbolAddress(&flp,  g_fl);

    static bool attr_set = false;
    if (!attr_set) {
        cudaFuncSetAttribute(k_scan, cudaFuncAttributeMaxDynamicSharedMemorySize,
                             (int)SMEM_BYTES);
        attr_set = true;
    }

    // Deterministic per-call init (exactly 3 memsets -> ncu -s5 hits k_scan)
    cudaMemsetAsync(h1fp, 0, sizeof(g_h1f), 0);
    cudaMemsetAsync(h2fp, 0, sizeof(g_h2f), 0);
    cudaMemsetAsync(flp,  0, sizeof(g_fl), 0);

    // One-time x transpose to fp16 fragments
    k_prep<<<2048, 256>>>(x);

    // Persistent fused 2-layer scan
    k_scan<<<GRID, NTHR, SMEM_BYTES>>>(W_ih0, W_hh0, W_ih1, W_hh1,
                                       b_ih0, b_hh0, b_ih1, b_hh1);

    // FC head
    k_fc<<<dim3(1, 4), 256>>>((const float*)h2pp, fc_w, fc_b, (float*)d_out);
}

// round 16
// speedup vs baseline: 1.1909x; 1.1909x over previous
#include <cuda_runtime.h>
#include <cuda_fp16.h>
#include <cstdint>
#include <cstddef>

constexpr int kB = 128, kT = 256, kI = 256, kH = 512, kO = 128;
constexpr int kBH = kB * kH;

// ---------------- Global scratch ----------------
__device__ uint4 g_xf[kT][2][2048];   // x fragments (K=256)
__device__ uint4 g_h1f[3][2][4096];   // h1 ring (K=512)
__device__ uint4 g_h2f[3][2][4096];   // h2 ring
__device__ float g_h2p[kBH];          // plain final h2 for FC
// Progress flags (epoch values, single writer per slot, st.release):
// g_fl[0][mcta][ncta] = it+1 after epi1(it); g_fl[1][mcta][ncta] = it after epi2(it).
__device__ unsigned g_fl[2][2][64];

constexpr int GRID = 128, NTHR = 512;

// ---------------- SMEM layout (bytes) ----------------
constexpr int SB_WHH0 = 0;        // 32 cols x 512 k fp16 = 32768 B
constexpr int SB_WI1  = 32768;
constexpr int SB_WHH1 = 65536;
constexpr int SB_WI0  = 98304;    // 32 cols x 256 k fp16 = 16384 B
constexpr int CEX_LD  = 34;
constexpr int SB_CEXA = 114688;   // float[4*64*34] = 34816 B
constexpr int SB_CEXB = 149504;
constexpr int SB_B1   = 184320;   // float[32]
constexpr int SB_B2   = 184448;
constexpr size_t SMEM_BYTES = 184576;

__device__ __forceinline__ float to_tf32(float x) {
    uint32_t u;
    asm("cvt.rna.tf32.f32 %0, %1;" : "=r"(u) : "f"(x));
    return __uint_as_float(u);
}

__device__ __forceinline__ void mma_f16(float* d, const uint32_t* a, const uint32_t* b) {
    asm volatile(
        "mma.sync.aligned.m16n8k16.row.col.f32.f16.f16.f32 "
        "{%0,%1,%2,%3}, {%4,%5,%6,%7}, {%8,%9}, {%0,%1,%2,%3};\n"
        : "+f"(d[0]), "+f"(d[1]), "+f"(d[2]), "+f"(d[3])
        : "r"(a[0]), "r"(a[1]), "r"(a[2]), "r"(a[3]), "r"(b[0]), "r"(b[1]));
}

__device__ __forceinline__ void mma_tf32(float* d, const uint32_t* a, const uint32_t* b) {
    asm volatile(
        "mma.sync.aligned.m16n8k8.row.col.f32.tf32.tf32.f32 "
        "{%0,%1,%2,%3}, {%4,%5,%6,%7}, {%8,%9}, {%0,%1,%2,%3};\n"
        : "+f"(d[0]), "+f"(d[1]), "+f"(d[2]), "+f"(d[3])
        : "r"(a[0]), "r"(a[1]), "r"(a[2]), "r"(a[3]), "r"(b[0]), "r"(b[1]));
}

// Fast activations (ex2.approx + rcp.approx): abs err ~3e-5 / ~6e-5.
__device__ __forceinline__ float fsigm(float x) {
    float t;
    asm("ex2.approx.f32 %0, %1;" : "=f"(t) : "f"(-x * 1.4426950408889634f));
    float r;
    asm("rcp.approx.f32 %0, %1;" : "=f"(r) : "f"(1.0f + t));
    return r;
}
__device__ __forceinline__ float ftanh(float x) {
    return 2.0f * fsigm(2.0f * x) - 1.0f;
}

// =====================================================================
// One-time x transpose into fp16 fragment layout.
// =====================================================================
__global__ void __launch_bounds__(256) k_prep(const float* __restrict__ x)
{
    __shared__ float tile[64][68];
    const int tid = threadIdx.x;
    const int u = blockIdx.x;
    const int ch = u & 3, mc = (u >> 2) & 1, t = u >> 3;

#pragma unroll
    for (int p = 0; p < 4; ++p) {
        const int v = tid + p * 256;
        const int r = v >> 4, k4 = v & 15;
        const float4 val = __ldg((const float4*)&x[
            (size_t)(mc * 64 + r) * (kT * kI) + (size_t)t * kI + ch * 64 + k4 * 4]);
        *(float4*)&tile[r][k4 * 4] = val;
    }
    __syncthreads();

    uint32_t* dst = (uint32_t*)&g_xf[t][mc][ch * 512];
#pragma unroll
    for (int p = 0; p < 8; ++p) {
        const int widx = tid + p * 256;
        const int gl   = widx >> 9;
        const int mt   = (widx >> 7) & 3;
        const int lane = (widx >> 2) & 31;
        const int reg  = widx & 3;
        const int r = mt * 16 + (lane >> 2) + ((reg & 1) << 3);
        const int k = gl * 16 + ((lane & 3) << 1) + ((reg >> 1) << 3);
        __half2 hv = __floats2half2_rn(tile[r][k], tile[r][k + 1]);
        dst[widx] = *(uint32_t*)&hv;
    }
}

// =====================================================================
// Persistent fused 2-layer LSTM scan, fp16 / fp32-acc (R14 structure).
// Chain-minimized: only Whh0 gemm + epi1 sit between f1 handoffs.
//   H1a (Whh0->acc1) -> epi1 + flag1
//   -> wait f2 -> H1b (Wih1->acc2; refill ring with h2) -> H2 (Whh1->acc2)
//   -> epi2 + flag2 -> X(it+1)->acc1 -> wait f1 + load h1 ring
//   (+ preload H1a's first b-frags inside the wait window).
// =====================================================================
__global__ void __launch_bounds__(NTHR, 1) k_scan(
    const float* __restrict__ Wih0, const float* __restrict__ Whh0,
    const float* __restrict__ Wih1, const float* __restrict__ Whh1,
    const float* __restrict__ bih0, const float* __restrict__ bhh0,
    const float* __restrict__ bih1, const float* __restrict__ bhh1)
{
    extern __shared__ char smc[];
    __half* WHH0h = (__half*)(smc + SB_WHH0);
    __half* WI1h  = (__half*)(smc + SB_WI1);
    __half* WHH1h = (__half*)(smc + SB_WHH1);
    __half* WI0h  = (__half*)(smc + SB_WI0);
    const uint32_t* BWH0 = (const uint32_t*)(smc + SB_WHH0);
    const uint32_t* BWI1 = (const uint32_t*)(smc + SB_WI1);
    const uint32_t* BWH1 = (const uint32_t*)(smc + SB_WHH1);
    const uint32_t* BWI0 = (const uint32_t*)(smc + SB_WI0);
    float* CEXA = (float*)(smc + SB_CEXA);
    float* CEXB = (float*)(smc + SB_CEXB);
    float* B1 = (float*)(smc + SB_B1);
    float* B2 = (float*)(smc + SB_B2);

    const int tid  = threadIdx.x;
    const int lane = tid & 31;
    const int w    = tid >> 5;
    const int kq   = w & 3;
    const int mw   = w >> 2;
    const int mcta = blockIdx.x & 1;
    const int ncta = blockIdx.x >> 1;
    const int hbase = ncta * 8;
    const int row0  = mcta * 64;

    // ---- Weight slices into SMEM as fp16 fragments ----
    for (int i = tid; i < 32 * 512; i += NTHR) {
        const int cc = i >> 9, k = i & 511;
        const int grow = (cc >> 3) * kH + hbase + (cc & 7);
        const int idx = ((((k >> 4) * 4 + (cc >> 3)) * 32 +
                          (((cc & 7) << 2) | ((k & 7) >> 1))) << 2) +
                        (((k >> 3) & 1) << 1) + (k & 1);
        WHH0h[idx] = __float2half(Whh0[grow * kH + k]);
        WI1h[idx]  = __float2half(Wih1[grow * kH + k]);
        WHH1h[idx] = __float2half(Whh1[grow * kH + k]);
    }
    for (int i = tid; i < 32 * 256; i += NTHR) {
        const int cc = i >> 8, k = i & 255;
        const int grow = (cc >> 3) * kH + hbase + (cc & 7);
        const int idx = ((((k >> 4) * 4 + (cc >> 3)) * 32 +
                          (((cc & 7) << 2) | ((k & 7) >> 1))) << 2) +
                        (((k >> 3) & 1) << 1) + (k & 1);
        WI0h[idx] = __float2half(Wih0[grow * kI + k]);
    }
    if (tid < 32) {
        const int grow = (tid >> 3) * kH + hbase + (tid & 7);
        B1[tid] = bih0[grow] + bhh0[grow];
        B2[tid] = bih1[grow] + bhh1[grow];
    }
    __syncthreads();

    const int er = tid >> 3;
    const int ej = tid & 7;
    const int hg  = ncta >> 1;
    const int hkl = ((ncta & 1) << 3) + ej;
    const int hmt = er >> 4;
    const int hr16 = er & 15;
    const int hlane = ((hr16 & 7) << 2) | ((hkl & 7) >> 1);
    const int hreg  = ((hr16 >> 3) & 1) | (((hkl >> 3) & 1) << 1);
    const int hhalf = hkl & 1;
    const int hflat = ((((hg * 4 + hmt) * 32 + hlane) * 4) + hreg) * 2 + hhalf;

    float c1s = 0.f, c2s = 0.f;

    auto wait_flags = [&](const unsigned* fb, unsigned need) {
        const unsigned* p = fb + kq * 16 + (lane & 15);
        bool ok;
        do {
            unsigned v;
            asm volatile("ld.acquire.gpu.u32 %0, [%1];"
                         : "=r"(v) : "l"(p) : "memory");
            ok = (v >= need);
        } while (__ballot_sync(0xffffffffu, ok) != 0xffffffffu);
    };

    uint4 ring[8];
    uint4 xa[4];
    uint2 bw0[2][4];   // preloaded Whh0 b-frags for H1a j=0,1
    float acc1[4][4], acc2[4][4];

    auto preload_bw0 = [&]() {
#pragma unroll
        for (int j = 0; j < 2; ++j)
#pragma unroll
            for (int t = 0; t < 4; ++t)
                bw0[j][t] = *(const uint2*)&BWH0[(((kq * 8 + j) * 4 + t) * 32 + lane) * 2];
    };

    // ---- Prologue: X(0) -> acc1, load h1 ring (buf 0, zeroed) ----
#pragma unroll
    for (int j = 0; j < 4; ++j)
        xa[j] = __ldcg(&g_xf[0][mcta][((kq * 4 + j) * 4 + mw) * 32 + lane]);
#pragma unroll
    for (int t = 0; t < 4; ++t)
#pragma unroll
        for (int q = 0; q < 4; ++q) acc1[t][q] = 0.f;
#pragma unroll
    for (int j = 0; j < 4; ++j) {
        const int g = kq * 4 + j;
        uint32_t au[4] = { xa[j].x, xa[j].y, xa[j].z, xa[j].w };
#pragma unroll
        for (int t = 0; t < 4; ++t) {
            const uint2 bb = *(const uint2*)&BWI0[((g * 4 + t) * 32 + lane) * 2];
            uint32_t bu[2] = { bb.x, bb.y };
            mma_f16(acc1[t], au, bu);
        }
    }
    {
        const uint4* h1b = &g_h1f[0][mcta][0];
#pragma unroll
        for (int j = 0; j < 8; ++j)
            ring[j] = __ldcg(&h1b[((kq * 8 + j) * 4 + mw) * 32 + lane]);
    }
    preload_bw0();

    int b_cur = 0, b_nxt = 1;

    for (int it = 0; it <= kT; ++it) {
        const bool do1 = (it < kT);
        const bool do2 = (it >= 1);

#pragma unroll
        for (int t = 0; t < 4; ++t)
#pragma unroll
            for (int q = 0; q < 4; ++q) acc2[t][q] = 0.f;

        // prefetch x frags for X(it+1)
        if (it + 1 < kT) {
#pragma unroll
            for (int j = 0; j < 4; ++j)
                xa[j] = __ldcg(&g_xf[it + 1][mcta][((kq * 4 + j) * 4 + mw) * 32 + lane]);
        }

        const int r  = mw * 16 + (lane >> 2);
        const int cb = (lane & 3) * 2;

        // ---- H1a: h1 @ Whh0 -> acc1 ONLY (ring preserved) ----
        if (do1) {
#pragma unroll
            for (int j = 0; j < 8; ++j) {
                const uint4 af = ring[j];
                uint32_t au[4] = { af.x, af.y, af.z, af.w };
                const int g = kq * 8 + j;
#pragma unroll
                for (int t = 0; t < 4; ++t) {
                    uint2 bb;
                    if (j < 2) bb = bw0[j][t];
                    else bb = *(const uint2*)&BWH0[((g * 4 + t) * 32 + lane) * 2];
                    uint32_t bu[2] = { bb.x, bb.y };
                    mma_f16(acc1[t], au, bu);
                }
            }

            // ---- epi1: reduce, cell update, store h1[it], flag1 ----
#pragma unroll
            for (int t = 0; t < 4; ++t) {
                float* cx = &CEXA[(kq * 64 + r) * CEX_LD + t * 8 + cb];
                *(float2*)cx                = make_float2(acc1[t][0], acc1[t][1]);
                *(float2*)(cx + 8 * CEX_LD) = make_float2(acc1[t][2], acc1[t][3]);
            }
            __syncthreads();
            float pre[4];
#pragma unroll
            for (int g = 0; g < 4; ++g) {
                float s = B1[g * 8 + ej];
#pragma unroll
                for (int q = 0; q < 4; ++q)
                    s += CEXA[(q * 64 + er) * CEX_LD + g * 8 + ej];
                pre[g] = s;
            }
            const float ig = fsigm(pre[0]), fg = fsigm(pre[1]);
            const float gg = ftanh(pre[2]), og = fsigm(pre[3]);
            const float cn = fg * c1s + ig * gg;
            c1s = cn;
            ((__half*)&g_h1f[b_nxt][mcta][0])[hflat] = __float2half(og * ftanh(cn));
            __syncthreads();
            if (tid == 0) {
                asm volatile("st.release.gpu.u32 [%0], %1;"
                             :: "l"(&g_fl[0][mcta][ncta]), "r"((unsigned)(it + 1))
                             : "memory");
            }
        }

        // ---- H1b + H2 + epi2 (off the f1 chain) ----
        if (do2) {
            if (it >= 2) wait_flags(&g_fl[1][mcta][0], (unsigned)(it - 1));
            const uint4* h2b = &g_h2f[b_cur][mcta][0];

            // H1b: h1 @ Wih1 -> acc2; refill ring[j] with h2 as consumed
#pragma unroll
            for (int j = 0; j < 8; ++j) {
                const uint4 af = ring[j];
                ring[j] = __ldcg(&h2b[((kq * 8 + j) * 4 + mw) * 32 + lane]);
                uint32_t au[4] = { af.x, af.y, af.z, af.w };
                const int g = kq * 8 + j;
#pragma unroll
                for (int t = 0; t < 4; ++t) {
                    const uint2 bb = *(const uint2*)&BWI1[((g * 4 + t) * 32 + lane) * 2];
                    uint32_t bu[2] = { bb.x, bb.y };
                    mma_f16(acc2[t], au, bu);
                }
            }

            // H2: h2 @ Whh1 -> acc2
#pragma unroll
            for (int j = 0; j < 8; ++j) {
                const uint4 af = ring[j];
                uint32_t au[4] = { af.x, af.y, af.z, af.w };
                const int g = kq * 8 + j;
#pragma unroll
                for (int t = 0; t < 4; ++t) {
                    const uint2 bb = *(const uint2*)&BWH1[((g * 4 + t) * 32 + lane) * 2];
                    uint32_t bu[2] = { bb.x, bb.y };
                    mma_f16(acc2[t], au, bu);
                }
            }

            // epi2
#pragma unroll
            for (int t = 0; t < 4; ++t) {
                float* cx = &CEXB[(kq * 64 + r) * CEX_LD + t * 8 + cb];
                *(float2*)cx                = make_float2(acc2[t][0], acc2[t][1]);
                *(float2*)(cx + 8 * CEX_LD) = make_float2(acc2[t][2], acc2[t][3]);
            }
            __syncthreads();
            float pre[4];
#pragma unroll
            for (int g = 0; g < 4; ++g) {
                float s = B2[g * 8 + ej];
#pragma unroll
                for (int q = 0; q < 4; ++q)
                    s += CEXB[(q * 64 + er) * CEX_LD + g * 8 + ej];
                pre[g] = s;
            }
            const float ig = fsigm(pre[0]), fg = fsigm(pre[1]);
            const float gg = ftanh(pre[2]), og = fsigm(pre[3]);
            const float cn = fg * c2s + ig * gg;
            c2s = cn;
            const float hv = og * ftanh(cn);
            ((__half*)&g_h2f[b_nxt][mcta][0])[hflat] = __float2half(hv);
            if (it == kT) g_h2p[(row0 + er) * kH + hbase + ej] = hv;
            __syncthreads();
            if (tid == 0) {
                asm volatile("st.release.gpu.u32 [%0], %1;"
                             :: "l"(&g_fl[1][mcta][ncta]), "r"((unsigned)it)
                             : "memory");
            }
        }

        // ---- X(it+1): static data, inside the wait window ----
        if (it + 1 < kT) {
#pragma unroll
            for (int t = 0; t < 4; ++t)
#pragma unroll
                for (int q = 0; q < 4; ++q) acc1[t][q] = 0.f;
#pragma unroll
            for (int j = 0; j < 4; ++j) {
                const int g = kq * 4 + j;
                uint32_t au[4] = { xa[j].x, xa[j].y, xa[j].z, xa[j].w };
#pragma unroll
                for (int t = 0; t < 4; ++t) {
                    const uint2 bb = *(const uint2*)&BWI0[((g * 4 + t) * 32 + lane) * 2];
                    uint32_t bu[2] = { bb.x, bb.y };
                    mma_f16(acc1[t], au, bu);
                }
            }
        }

        // ---- handoff: preload H1a b-frags, wait f1, load h1 ring ----
        if (it < kT) {
            preload_bw0();
            wait_flags(&g_fl[0][mcta][0], (unsigned)(it + 1));
            const uint4* h1b = &g_h1f[b_nxt][mcta][0];
#pragma unroll
            for (int j = 0; j < 8; ++j)
                ring[j] = __ldcg(&h1b[((kq * 8 + j) * 4 + mw) * 32 + lane]);
        }

        b_cur = b_nxt;
        b_nxt = b_nxt + 1;
        if (b_nxt == 3) b_nxt = 0;
    }
}

// =====================================================================
// FC head: out = h2_final @ fc_w^T + fc_b
// =====================================================================
__global__ __launch_bounds__(256) void k_fc(
    const float* __restrict__ A0, const float* __restrict__ W0,
    const float* __restrict__ bias0, float* __restrict__ outp)
{
    __shared__ float Asf[512];
    __shared__ float Bsf[2048];

    const int tid  = threadIdx.x;
    const int lane = tid & 31;
    const int w    = tid >> 5;
    const int mw   = w >> 2;
    const int nw   = w & 3;
    const int mtile = blockIdx.y;

    float acc[4][4];
#pragma unroll
    for (int j = 0; j < 4; j++)
#pragma unroll
        for (int q = 0; q < 4; q++) acc[j][q] = 0.0f;

    const int a_r  = tid >> 3;
    const int a_kk = (tid & 7) * 2;
    const int b_n   = tid >> 1;
    const int b_kk8 = (tid & 1) * 8;

#pragma unroll 1
    for (int kt = 0; kt < kH; kt += 16) {
        {
            const int gm = mtile * 32 + a_r;
            const float2 v = *(const float2*)&A0[(size_t)gm * kH + kt + a_kk];
            const float vv[2] = { v.x, v.y };
#pragma unroll
            for (int e = 0; e < 2; ++e) {
                const int k = a_kk + e;
                const int g = (k >> 3) * 2 + (a_r >> 4);
                const int ln = ((a_r & 7) << 2) | (k & 3);
                const int comp = ((a_r >> 3) & 1) | (((k >> 2) & 1) << 1);
                Asf[(g * 32 + ln) * 4 + comp] = to_tf32(vv[e]);
            }
        }
        {
            const float4* p = (const float4*)&W0[(size_t)b_n * kH + kt + b_kk8];
            const float4 v0 = p[0], v1 = p[1];
            const float vv[8] = { v0.x, v0.y, v0.z, v0.w, v1.x, v1.y, v1.z, v1.w };
#pragma unroll
            for (int e = 0; e < 8; ++e) {
                const int k = b_kk8 + e;
                const int g = (k >> 3) * 16 + (b_n >> 3);
                const int ln = ((b_n & 7) << 2) | (k & 3);
                const int comp = (k >> 2) & 1;
                Bsf[(g * 32 + ln) * 2 + comp] = to_tf32(vv[e]);
            }
        }
        __syncthreads();

#pragma unroll
        for (int k8 = 0; k8 < 2; ++k8) {
            const float4 af = *(const float4*)&Asf[((k8 * 2 + mw) * 32 + lane) * 4];
            uint32_t au[4] = { __float_as_uint(af.x), __float_as_uint(af.y),
                               __float_as_uint(af.z), __float_as_uint(af.w) };
#pragma unroll
            for (int j = 0; j < 4; ++j) {
                const float2 b = *(const float2*)&Bsf[((k8 * 16 + nw * 4 + j) * 32 + lane) * 2];
                uint32_t bu[2] = { __float_as_uint(b.x), __float_as_uint(b.y) };
                mma_tf32(acc[j], au, bu);
            }
        }
        __syncthreads();
    }

    const int gr = mtile * 32 + mw * 16 + (lane >> 2);
    const int cbase = nw * 32 + (lane & 3) * 2;
#pragma unroll
    for (int j = 0; j < 4; j++) {
        const int c0 = cbase + j * 8;
        const float bv0 = bias0[c0];
        const float bv1 = bias0[c0 + 1];
        outp[(size_t)gr * kO + c0]           = acc[j][0] + bv0;
        outp[(size_t)gr * kO + c0 + 1]       = acc[j][1] + bv1;
        outp[(size_t)(gr + 8) * kO + c0]     = acc[j][2] + bv0;
        outp[(size_t)(gr + 8) * kO + c0 + 1] = acc[j][3] + bv1;
    }
}

extern "C" void kernel_launch(void* const* d_in, const int* in_sizes, int n_in,
                              void* d_out, int out_size)
{
    const float* x     = (const float*)d_in[0];
    const float* W_ih0 = (const float*)d_in[1];
    const float* W_hh0 = (const float*)d_in[2];
    const float* b_ih0 = (const float*)d_in[3];
    const float* b_hh0 = (const float*)d_in[4];
    const float* W_ih1 = (const float*)d_in[5];
    const float* W_hh1 = (const float*)d_in[6];
    const float* b_ih1 = (const float*)d_in[7];
    const float* b_hh1 = (const float*)d_in[8];
    const float* fc_w  = (const float*)d_in[9];
    const float* fc_b  = (const float*)d_in[10];

    void *h1fp, *h2fp, *flp;
    cudaGetSymbolAddress(&h1fp, g_h1f);
    cudaGetSymbolAddress(&h2fp, g_h2f);
    cudaGetSymbolAddress(&flp,  g_fl);
    void* h2pp;
    cudaGetSymbolAddress(&h2pp, g_h2p);

    static bool attr_set = false;
    if (!attr_set) {
        cudaFuncSetAttribute(k_scan, cudaFuncAttributeMaxDynamicSharedMemorySize,
                             (int)SMEM_BYTES);
        attr_set = true;
    }

    // Deterministic per-call init
    cudaMemsetAsync(h1fp, 0, sizeof(g_h1f), 0);
    cudaMemsetAsync(h2fp, 0, sizeof(g_h2f), 0);
    cudaMemsetAsync(flp,  0, sizeof(g_fl), 0);

    // One-time x transpose to fp16 fragments
    k_prep<<<2048, 256>>>(x);

    // Persistent fused 2-layer scan
    k_scan<<<GRID, NTHR, SMEM_BYTES>>>(W_ih0, W_hh0, W_ih1, W_hh1,
                                       b_ih0, b_hh0, b_ih1, b_hh1);

    // FC head
    k_fc<<<dim3(1, 4), 256>>>((const float*)h2pp, fc_w, fc_b, (float*)d_out);
}

// round 17
// speedup vs baseline: 1.1920x; 1.0009x over previous
#include <cuda_runtime.h>
#include <cuda_fp16.h>
#include <cstdint>
#include <cstddef>

constexpr int kB = 128, kT = 256, kI = 256, kH = 512, kO = 128;
constexpr int kBH = kB * kH;

// ---------------- Global scratch ----------------
__device__ uint4 g_xf[kT][2][2048];   // x fragments (K=256)
__device__ uint4 g_h1f[3][2][4096];   // h1 ring (K=512)
__device__ uint4 g_h2f[3][2][4096];   // h2 ring
__device__ float g_h2p[kBH];          // plain final h2 for FC
// Progress flags (epoch values, single writer per slot, st.release):
// g_fl[0][mcta][ncta] = it+1 after epi1(it); g_fl[1][mcta][ncta] = it after epi2(it).
__device__ unsigned g_fl[2][2][64];

constexpr int GRID = 128, NTHR = 512;

// ---------------- SMEM layout (bytes) ----------------
constexpr int SB_WHH0 = 0;        // 32 cols x 512 k fp16 = 32768 B
constexpr int SB_WI1  = 32768;
constexpr int SB_WHH1 = 65536;
constexpr int SB_WI0  = 98304;    // 32 cols x 256 k fp16 = 16384 B
constexpr int CEX_LD  = 34;
constexpr int SB_CEXA = 114688;   // float[4*64*34] = 34816 B
constexpr int SB_CEXB = 149504;
constexpr int SB_B1   = 184320;   // float[32]
constexpr int SB_B2   = 184448;
constexpr size_t SMEM_BYTES = 184576;

__device__ __forceinline__ float to_tf32(float x) {
    uint32_t u;
    asm("cvt.rna.tf32.f32 %0, %1;" : "=r"(u) : "f"(x));
    return __uint_as_float(u);
}

__device__ __forceinline__ void mma_f16(float* d, const uint32_t* a, const uint32_t* b) {
    asm volatile(
        "mma.sync.aligned.m16n8k16.row.col.f32.f16.f16.f32 "
        "{%0,%1,%2,%3}, {%4,%5,%6,%7}, {%8,%9}, {%0,%1,%2,%3};\n"
        : "+f"(d[0]), "+f"(d[1]), "+f"(d[2]), "+f"(d[3])
        : "r"(a[0]), "r"(a[1]), "r"(a[2]), "r"(a[3]), "r"(b[0]), "r"(b[1]));
}

__device__ __forceinline__ void mma_tf32(float* d, const uint32_t* a, const uint32_t* b) {
    asm volatile(
        "mma.sync.aligned.m16n8k8.row.col.f32.tf32.tf32.f32 "
        "{%0,%1,%2,%3}, {%4,%5,%6,%7}, {%8,%9}, {%0,%1,%2,%3};\n"
        : "+f"(d[0]), "+f"(d[1]), "+f"(d[2]), "+f"(d[3])
        : "r"(a[0]), "r"(a[1]), "r"(a[2]), "r"(a[3]), "r"(b[0]), "r"(b[1]));
}

// Fast activations (ex2.approx + rcp.approx): abs err ~3e-5 / ~6e-5.
__device__ __forceinline__ float fsigm(float x) {
    float t;
    asm("ex2.approx.f32 %0, %1;" : "=f"(t) : "f"(-x * 1.4426950408889634f));
    float r;
    asm("rcp.approx.f32 %0, %1;" : "=f"(r) : "f"(1.0f + t));
    return r;
}
__device__ __forceinline__ float ftanh(float x) {
    return 2.0f * fsigm(2.0f * x) - 1.0f;
}

// Trivial kernel: shifts the ncu capture slot (-s 5) so the 6th kernel
// launch is k_scan instead of k_prep. Does no work; graph-safe.
__global__ void k_slot() {}

// =====================================================================
// One-time x transpose into fp16 fragment layout.
// =====================================================================
__global__ void __launch_bounds__(256) k_prep(const float* __restrict__ x)
{
    __shared__ float tile[64][68];
    const int tid = threadIdx.x;
    const int u = blockIdx.x;
    const int ch = u & 3, mc = (u >> 2) & 1, t = u >> 3;

#pragma unroll
    for (int p = 0; p < 4; ++p) {
        const int v = tid + p * 256;
        const int r = v >> 4, k4 = v & 15;
        const float4 val = __ldg((const float4*)&x[
            (size_t)(mc * 64 + r) * (kT * kI) + (size_t)t * kI + ch * 64 + k4 * 4]);
        *(float4*)&tile[r][k4 * 4] = val;
    }
    __syncthreads();

    uint32_t* dst = (uint32_t*)&g_xf[t][mc][ch * 512];
#pragma unroll
    for (int p = 0; p < 8; ++p) {
        const int widx = tid + p * 256;
        const int gl   = widx >> 9;
        const int mt   = (widx >> 7) & 3;
        const int lane = (widx >> 2) & 31;
        const int reg  = widx & 3;
        const int r = mt * 16 + (lane >> 2) + ((reg & 1) << 3);
        const int k = gl * 16 + ((lane & 3) << 1) + ((reg >> 1) << 3);
        __half2 hv = __floats2half2_rn(tile[r][k], tile[r][k + 1]);
        dst[widx] = *(uint32_t*)&hv;
    }
}

// =====================================================================
// Persistent fused 2-layer LSTM scan, fp16 / fp32-acc (R16 structure).
// =====================================================================
__global__ void __launch_bounds__(NTHR, 1) k_scan(
    const float* __restrict__ Wih0, const float* __restrict__ Whh0,
    const float* __restrict__ Wih1, const float* __restrict__ Whh1,
    const float* __restrict__ bih0, const float* __restrict__ bhh0,
    const float* __restrict__ bih1, const float* __restrict__ bhh1)
{
    extern __shared__ char smc[];
    __half* WHH0h = (__half*)(smc + SB_WHH0);
    __half* WI1h  = (__half*)(smc + SB_WI1);
    __half* WHH1h = (__half*)(smc + SB_WHH1);
    __half* WI0h  = (__half*)(smc + SB_WI0);
    const uint32_t* BWH0 = (const uint32_t*)(smc + SB_WHH0);
    const uint32_t* BWI1 = (const uint32_t*)(smc + SB_WI1);
    const uint32_t* BWH1 = (const uint32_t*)(smc + SB_WHH1);
    const uint32_t* BWI0 = (const uint32_t*)(smc + SB_WI0);
    float* CEXA = (float*)(smc + SB_CEXA);
    float* CEXB = (float*)(smc + SB_CEXB);
    float* B1 = (float*)(smc + SB_B1);
    float* B2 = (float*)(smc + SB_B2);

    const int tid  = threadIdx.x;
    const int lane = tid & 31;
    const int w    = tid >> 5;
    const int kq   = w & 3;
    const int mw   = w >> 2;
    const int mcta = blockIdx.x & 1;
    const int ncta = blockIdx.x >> 1;
    const int hbase = ncta * 8;
    const int row0  = mcta * 64;

    // ---- Weight slices into SMEM as fp16 fragments ----
    for (int i = tid; i < 32 * 512; i += NTHR) {
        const int cc = i >> 9, k = i & 511;
        const int grow = (cc >> 3) * kH + hbase + (cc & 7);
        const int idx = ((((k >> 4) * 4 + (cc >> 3)) * 32 +
                          (((cc & 7) << 2) | ((k & 7) >> 1))) << 2) +
                        (((k >> 3) & 1) << 1) + (k & 1);
        WHH0h[idx] = __float2half(Whh0[grow * kH + k]);
        WI1h[idx]  = __float2half(Wih1[grow * kH + k]);
        WHH1h[idx] = __float2half(Whh1[grow * kH + k]);
    }
    for (int i = tid; i < 32 * 256; i += NTHR) {
        const int cc = i >> 8, k = i & 255;
        const int grow = (cc >> 3) * kH + hbase + (cc & 7);
        const int idx = ((((k >> 4) * 4 + (cc >> 3)) * 32 +
                          (((cc & 7) << 2) | ((k & 7) >> 1))) << 2) +
                        (((k >> 3) & 1) << 1) + (k & 1);
        WI0h[idx] = __float2half(Wih0[grow * kI + k]);
    }
    if (tid < 32) {
        const int grow = (tid >> 3) * kH + hbase + (tid & 7);
        B1[tid] = bih0[grow] + bhh0[grow];
        B2[tid] = bih1[grow] + bhh1[grow];
    }
    __syncthreads();

    const int er = tid >> 3;
    const int ej = tid & 7;
    const int hg  = ncta >> 1;
    const int hkl = ((ncta & 1) << 3) + ej;
    const int hmt = er >> 4;
    const int hr16 = er & 15;
    const int hlane = ((hr16 & 7) << 2) | ((hkl & 7) >> 1);
    const int hreg  = ((hr16 >> 3) & 1) | (((hkl >> 3) & 1) << 1);
    const int hhalf = hkl & 1;
    const int hflat = ((((hg * 4 + hmt) * 32 + hlane) * 4) + hreg) * 2 + hhalf;

    float c1s = 0.f, c2s = 0.f;

    auto wait_flags = [&](const unsigned* fb, unsigned need) {
        const unsigned* p = fb + kq * 16 + (lane & 15);
        bool ok;
        do {
            unsigned v;
            asm volatile("ld.acquire.gpu.u32 %0, [%1];"
                         : "=r"(v) : "l"(p) : "memory");
            ok = (v >= need);
        } while (__ballot_sync(0xffffffffu, ok) != 0xffffffffu);
    };

    uint4 ring[8];
    uint4 xa[4];
    uint2 bw0[2][4];   // preloaded Whh0 b-frags for H1a j=0,1
    float acc1[4][4], acc2[4][4];

    auto preload_bw0 = [&]() {
#pragma unroll
        for (int j = 0; j < 2; ++j)
#pragma unroll
            for (int t = 0; t < 4; ++t)
                bw0[j][t] = *(const uint2*)&BWH0[(((kq * 8 + j) * 4 + t) * 32 + lane) * 2];
    };

    // ---- Prologue: X(0) -> acc1, load h1 ring (buf 0, zeroed) ----
#pragma unroll
    for (int j = 0; j < 4; ++j)
        xa[j] = __ldcg(&g_xf[0][mcta][((kq * 4 + j) * 4 + mw) * 32 + lane]);
#pragma unroll
    for (int t = 0; t < 4; ++t)
#pragma unroll
        for (int q = 0; q < 4; ++q) acc1[t][q] = 0.f;
#pragma unroll
    for (int j = 0; j < 4; ++j) {
        const int g = kq * 4 + j;
        uint32_t au[4] = { xa[j].x, xa[j].y, xa[j].z, xa[j].w };
#pragma unroll
        for (int t = 0; t < 4; ++t) {
            const uint2 bb = *(const uint2*)&BWI0[((g * 4 + t) * 32 + lane) * 2];
            uint32_t bu[2] = { bb.x, bb.y };
            mma_f16(acc1[t], au, bu);
        }
    }
    {
        const uint4* h1b = &g_h1f[0][mcta][0];
#pragma unroll
        for (int j = 0; j < 8; ++j)
            ring[j] = __ldcg(&h1b[((kq * 8 + j) * 4 + mw) * 32 + lane]);
    }
    preload_bw0();

    int b_cur = 0, b_nxt = 1;

    for (int it = 0; it <= kT; ++it) {
        const bool do1 = (it < kT);
        const bool do2 = (it >= 1);

#pragma unroll
        for (int t = 0; t < 4; ++t)
#pragma unroll
            for (int q = 0; q < 4; ++q) acc2[t][q] = 0.f;

        // prefetch x frags for X(it+1)
        if (it + 1 < kT) {
#pragma unroll
            for (int j = 0; j < 4; ++j)
                xa[j] = __ldcg(&g_xf[it + 1][mcta][((kq * 4 + j) * 4 + mw) * 32 + lane]);
        }

        const int r  = mw * 16 + (lane >> 2);
        const int cb = (lane & 3) * 2;

        // ---- H1a: h1 @ Whh0 -> acc1 ONLY (ring preserved) ----
        if (do1) {
#pragma unroll
            for (int j = 0; j < 8; ++j) {
                const uint4 af = ring[j];
                uint32_t au[4] = { af.x, af.y, af.z, af.w };
                const int g = kq * 8 + j;
#pragma unroll
                for (int t = 0; t < 4; ++t) {
                    uint2 bb;
                    if (j < 2) bb = bw0[j][t];
                    else bb = *(const uint2*)&BWH0[((g * 4 + t) * 32 + lane) * 2];
                    uint32_t bu[2] = { bb.x, bb.y };
                    mma_f16(acc1[t], au, bu);
                }
            }

            // ---- epi1: reduce, cell update, store h1[it], flag1 ----
#pragma unroll
            for (int t = 0; t < 4; ++t) {
                float* cx = &CEXA[(kq * 64 + r) * CEX_LD + t * 8 + cb];
                *(float2*)cx                = make_float2(acc1[t][0], acc1[t][1]);
                *(float2*)(cx + 8 * CEX_LD) = make_float2(acc1[t][2], acc1[t][3]);
            }
            __syncthreads();
            float pre[4];
#pragma unroll
            for (int g = 0; g < 4; ++g) {
                float s = B1[g * 8 + ej];
#pragma unroll
                for (int q = 0; q < 4; ++q)
                    s += CEXA[(q * 64 + er) * CEX_LD + g * 8 + ej];
                pre[g] = s;
            }
            const float ig = fsigm(pre[0]), fg = fsigm(pre[1]);
            const float gg = ftanh(pre[2]), og = fsigm(pre[3]);
            const float cn = fg * c1s + ig * gg;
            c1s = cn;
            ((__half*)&g_h1f[b_nxt][mcta][0])[hflat] = __float2half(og * ftanh(cn));
            __syncthreads();
            if (tid == 0) {
                asm volatile("st.release.gpu.u32 [%0], %1;"
                             :: "l"(&g_fl[0][mcta][ncta]), "r"((unsigned)(it + 1))
                             : "memory");
            }
        }

        // ---- H1b + H2 + epi2 (off the f1 chain) ----
        if (do2) {
            if (it >= 2) wait_flags(&g_fl[1][mcta][0], (unsigned)(it - 1));
            const uint4* h2b = &g_h2f[b_cur][mcta][0];

            // H1b: h1 @ Wih1 -> acc2; refill ring[j] with h2 as consumed
#pragma unroll
            for (int j = 0; j < 8; ++j) {
                const uint4 af = ring[j];
                ring[j] = __ldcg(&h2b[((kq * 8 + j) * 4 + mw) * 32 + lane]);
                uint32_t au[4] = { af.x, af.y, af.z, af.w };
                const int g = kq * 8 + j;
#pragma unroll
                for (int t = 0; t < 4; ++t) {
                    const uint2 bb = *(const uint2*)&BWI1[((g * 4 + t) * 32 + lane) * 2];
                    uint32_t bu[2] = { bb.x, bb.y };
                    mma_f16(acc2[t], au, bu);
                }
            }

            // H2: h2 @ Whh1 -> acc2
#pragma unroll
            for (int j = 0; j < 8; ++j) {
                const uint4 af = ring[j];
                uint32_t au[4] = { af.x, af.y, af.z, af.w };
                const int g = kq * 8 + j;
#pragma unroll
                for (int t = 0; t < 4; ++t) {
                    const uint2 bb = *(const uint2*)&BWH1[((g * 4 + t) * 32 + lane) * 2];
                    uint32_t bu[2] = { bb.x, bb.y };
                    mma_f16(acc2[t], au, bu);
                }
            }

            // epi2
#pragma unroll
            for (int t = 0; t < 4; ++t) {
                float* cx = &CEXB[(kq * 64 + r) * CEX_LD + t * 8 + cb];
                *(float2*)cx                = make_float2(acc2[t][0], acc2[t][1]);
                *(float2*)(cx + 8 * CEX_LD) = make_float2(acc2[t][2], acc2[t][3]);
            }
            __syncthreads();
            float pre[4];
#pragma unroll
            for (int g = 0; g < 4; ++g) {
                float s = B2[g * 8 + ej];
#pragma unroll
                for (int q = 0; q < 4; ++q)
                    s += CEXB[(q * 64 + er) * CEX_LD + g * 8 + ej];
                pre[g] = s;
            }
            const float ig = fsigm(pre[0]), fg = fsigm(pre[1]);
            const float gg = ftanh(pre[2]), og = fsigm(pre[3]);
            const float cn = fg * c2s + ig * gg;
            c2s = cn;
            const float hv = og * ftanh(cn);
            ((__half*)&g_h2f[b_nxt][mcta][0])[hflat] = __float2half(hv);
            if (it == kT) g_h2p[(row0 + er) * kH + hbase + ej] = hv;
            __syncthreads();
            if (tid == 0) {
                asm volatile("st.release.gpu.u32 [%0], %1;"
                             :: "l"(&g_fl[1][mcta][ncta]), "r"((unsigned)it)
                             : "memory");
            }
        }

        // ---- X(it+1): static data, inside the wait window ----
        if (it + 1 < kT) {
#pragma unroll
            for (int t = 0; t < 4; ++t)
#pragma unroll
                for (int q = 0; q < 4; ++q) acc1[t][q] = 0.f;
#pragma unroll
            for (int j = 0; j < 4; ++j) {
                const int g = kq * 4 + j;
                uint32_t au[4] = { xa[j].x, xa[j].y, xa[j].z, xa[j].w };
#pragma unroll
                for (int t = 0; t < 4; ++t) {
                    const uint2 bb = *(const uint2*)&BWI0[((g * 4 + t) * 32 + lane) * 2];
                    uint32_t bu[2] = { bb.x, bb.y };
                    mma_f16(acc1[t], au, bu);
                }
            }
        }

        // ---- handoff: preload H1a b-frags, wait f1, load h1 ring ----
        if (it < kT) {
            preload_bw0();
            wait_flags(&g_fl[0][mcta][0], (unsigned)(it + 1));
            const uint4* h1b = &g_h1f[b_nxt][mcta][0];
#pragma unroll
            for (int j = 0; j < 8; ++j)
                ring[j] = __ldcg(&h1b[((kq * 8 + j) * 4 + mw) * 32 + lane]);
        }

        b_cur = b_nxt;
        b_nxt = b_nxt + 1;
        if (b_nxt == 3) b_nxt = 0;
    }
}

// =====================================================================
// FC head: out = h2_final @ fc_w^T + fc_b
// =====================================================================
__global__ __launch_bounds__(256) void k_fc(
    const float* __restrict__ A0, const float* __restrict__ W0,
    const float* __restrict__ bias0, float* __restrict__ outp)
{
    __shared__ float Asf[512];
    __shared__ float Bsf[2048];

    const int tid  = threadIdx.x;
    const int lane = tid & 31;
    const int w    = tid >> 5;
    const int mw   = w >> 2;
    const int nw   = w & 3;
    const int mtile = blockIdx.y;

    float acc[4][4];
#pragma unroll
    for (int j = 0; j < 4; j++)
#pragma unroll
        for (int q = 0; q < 4; q++) acc[j][q] = 0.0f;

    const int a_r  = tid >> 3;
    const int a_kk = (tid & 7) * 2;
    const int b_n   = tid >> 1;
    const int b_kk8 = (tid & 1) * 8;

#pragma unroll 1
    for (int kt = 0; kt < kH; kt += 16) {
        {
            const int gm = mtile * 32 + a_r;
            const float2 v = *(const float2*)&A0[(size_t)gm * kH + kt + a_kk];
            const float vv[2] = { v.x, v.y };
#pragma unroll
            for (int e = 0; e < 2; ++e) {
                const int k = a_kk + e;
                const int g = (k >> 3) * 2 + (a_r >> 4);
                const int ln = ((a_r & 7) << 2) | (k & 3);
                const int comp = ((a_r >> 3) & 1) | (((k >> 2) & 1) << 1);
                Asf[(g * 32 + ln) * 4 + comp] = to_tf32(vv[e]);
            }
        }
        {
            const float4* p = (const float4*)&W0[(size_t)b_n * kH + kt + b_kk8];
            const float4 v0 = p[0], v1 = p[1];
            const float vv[8] = { v0.x, v0.y, v0.z, v0.w, v1.x, v1.y, v1.z, v1.w };
#pragma unroll
            for (int e = 0; e < 8; ++e) {
                const int k = b_kk8 + e;
                const int g = (k >> 3) * 16 + (b_n >> 3);
                const int ln = ((b_n & 7) << 2) | (k & 3);
                const int comp = (k >> 2) & 1;
                Bsf[(g * 32 + ln) * 2 + comp] = to_tf32(vv[e]);
            }
        }
        __syncthreads();

#pragma unroll
        for (int k8 = 0; k8 < 2; ++k8) {
            const float4 af = *(const float4*)&Asf[((k8 * 2 + mw) * 32 + lane) * 4];
            uint32_t au[4] = { __float_as_uint(af.x), __float_as_uint(af.y),
                               __float_as_uint(af.z), __float_as_uint(af.w) };
#pragma unroll
            for (int j = 0; j < 4; ++j) {
                const float2 b = *(const float2*)&Bsf[((k8 * 16 + nw * 4 + j) * 32 + lane) * 2];
                uint32_t bu[2] = { __float_as_uint(b.x), __float_as_uint(b.y) };
                mma_tf32(acc[j], au, bu);
            }
        }
        __syncthreads();
    }

    const int gr = mtile * 32 + mw * 16 + (lane >> 2);
    const int cbase = nw * 32 + (lane & 3) * 2;
#pragma unroll
    for (int j = 0; j < 4; j++) {
        const int c0 = cbase + j * 8;
        const float bv0 = bias0[c0];
        const float bv1 = bias0[c0 + 1];
        outp[(size_t)gr * kO + c0]           = acc[j][0] + bv0;
        outp[(size_t)gr * kO + c0 + 1]       = acc[j][1] + bv1;
        outp[(size_t)(gr + 8) * kO + c0]     = acc[j][2] + bv0;
        outp[(size_t)(gr + 8) * kO + c0 + 1] = acc[j][3] + bv1;
    }
}

extern "C" void kernel_launch(void* const* d_in, const int* in_sizes, int n_in,
                              void* d_out, int out_size)
{
    const float* x     = (const float*)d_in[0];
    const float* W_ih0 = (const float*)d_in[1];
    const float* W_hh0 = (const float*)d_in[2];
    const float* b_ih0 = (const float*)d_in[3];
    const float* b_hh0 = (const float*)d_in[4];
    const float* W_ih1 = (const float*)d_in[5];
    const float* W_hh1 = (const float*)d_in[6];
    const float* b_ih1 = (const float*)d_in[7];
    const float* b_hh1 = (const float*)d_in[8];
    const float* fc_w  = (const float*)d_in[9];
    const float* fc_b  = (const float*)d_in[10];

    void *h1fp, *h2fp, *flp, *h2pp;
    cudaGetSymbolAddress(&h1fp, g_h1f);
    cudaGetSymbolAddress(&h2fp, g_h2f);
    cudaGetSymbolAddress(&flp,  g_fl);
    cudaGetSymbolAddress(&h2pp, g_h2p);

    static bool attr_set = false;
    if (!attr_set) {
        cudaFuncSetAttribute(k_scan, cudaFuncAttributeMaxDynamicSharedMemorySize,
                             (int)SMEM_BYTES);
        attr_set = true;
    }

    // Deterministic per-call init
    cudaMemsetAsync(h1fp, 0, sizeof(g_h1f), 0);
    cudaMemsetAsync(h2fp, 0, sizeof(g_h2f), 0);
    cudaMemsetAsync(flp,  0, sizeof(g_fl), 0);

    // Slot-shift kernel (diagnostic: moves ncu -s5 capture onto k_scan)
    k_slot<<<1, 32>>>();

    // One-time x transpose to fp16 fragments
    k_prep<<<2048, 256>>>(x);

    // Persistent fused 2-layer scan
    k_scan<<<GRID, NTHR, SMEM_BYTES>>>(W_ih0, W_hh0, W_ih1, W_hh1,
                                       b_ih0, b_hh0, b_ih1, b_hh1);

    // FC head
    k_fc<<<dim3(1, 4), 256>>>((const float*)h2pp, fc_w, fc_b, (float*)d_out);
}